// round 3
// baseline (speedup 1.0000x reference)
#include <cuda_runtime.h>

#define B 256
#define S 512
#define IN_F 32
#define H 256
#define G3 768
#define D_OUT 32
#define NSTATE 4
#define PRED 96

#define GRU_CTAS 128
#define ROWTILES 16
#define STRIPS 8

// GRU smem layout (floats)
#define WROW 68                    // 68 % 32 == 4 -> conflict-free within 8-lane phase
#define QSTRIDE (96 * WROW)        // 6528, one K-quarter of the 96 W rows
#define SH_STRIDE 256
#define RED_STRIDE 33
#define RED_OFF (4 * QSTRIDE + 16 * SH_STRIDE)          // 26112 + 4096
#define SMEM_FLOATS (RED_OFF + 2 * 4 * 24 * RED_STRIDE) // + 6336
#define SMEM_BYTES (SMEM_FLOATS * 4)                    // 146176 B

// -------- packed f32x2 helpers --------
__device__ __forceinline__ unsigned long long fma2(unsigned long long a,
                                                   unsigned long long b,
                                                   unsigned long long c)
{
    unsigned long long d;
    asm("fma.rn.f32x2 %0, %1, %2, %3;" : "=l"(d) : "l"(a), "l"(b), "l"(c));
    return d;
}
__device__ __forceinline__ unsigned long long dup2(float x)
{
    unsigned long long d;
    unsigned r = __float_as_uint(x);
    asm("mov.b64 %0, {%1, %1};" : "=l"(d) : "r"(r));
    return d;
}
__device__ __forceinline__ float hsum2(unsigned long long a)
{
    unsigned lo, hi;
    asm("mov.b64 {%0, %1}, %2;" : "=r"(lo), "=r"(hi) : "l"(a));
    return __uint_as_float(lo) + __uint_as_float(hi);
}
__device__ __forceinline__ void unpack2(unsigned long long a, float& lo, float& hi)
{
    unsigned l, h;
    asm("mov.b64 {%0, %1}, %2;" : "=r"(l), "=r"(h) : "l"(a));
    lo = __uint_as_float(l); hi = __uint_as_float(h);
}
__device__ __forceinline__ float tanh_ap(float x)
{
    float y;
    asm("tanh.approx.f32 %0, %1;" : "=f"(y) : "f"(x));
    return y;
}
__device__ __forceinline__ float sigmoid_ap(float x)
{
    return 0.5f * tanh_ap(0.5f * x) + 0.5f;
}

// -------- scratch --------
__device__ float g_xp[(size_t)B * S * G3];
__device__ float g_h1s[(size_t)B * S * H];
__device__ float g_hbuf[2 * B * H];
__device__ float g_h2[B * H];
__device__ unsigned g_bar_count[ROWTILES];
__device__ unsigned g_bar_gen[ROWTILES];

// -------- SGEMM: out[M,N] = A[M,K] @ W[N,K]^T + bias[N] --------
// Tile 128(M) x 64(N), 256 threads, 8x4 micro-tile, packed f32x2.
// Requires M%128==0, N%64==0, K%16==0.
__global__ __launch_bounds__(256) void gemm_nt_bias(
    const float* __restrict__ A, const float* __restrict__ W,
    const float* __restrict__ bias, float* __restrict__ out,
    int M, int N, int K)
{
    __shared__ float As[16 * 128];   // [k][m]
    __shared__ float Ws[16 * 64];    // [k][n]
    const int n0 = blockIdx.x * 64;
    const int m0 = blockIdx.y * 128;
    const int tid = threadIdx.x;
    const int tx = tid & 15;    // col group (4 cols)
    const int ty = tid >> 4;    // row group (8 rows)

    // load maps (conflict-free STS: lane-consecutive m/n index)
    const int war = tid & 63;            // W row (n)
    const int wak = (tid >> 6) << 2;     // W k offset

    unsigned long long acc[8][2];
#pragma unroll
    for (int i = 0; i < 8; i++) { acc[i][0] = 0ull; acc[i][1] = 0ull; }

    for (int k0 = 0; k0 < K; k0 += 16) {
        // A: 512 float4 per slab, 2 per thread; f4id = r*256+tid,
        // ar = f4id & 127, ak = (f4id>>7)*4
#pragma unroll
        for (int r = 0; r < 2; r++) {
            int f4id = r * 256 + tid;
            int ar = f4id & 127;
            int ak = (f4id >> 7) << 2;
            float4 a = *(const float4*)&A[(size_t)(m0 + ar) * K + k0 + ak];
            As[(ak + 0) * 128 + ar] = a.x;
            As[(ak + 1) * 128 + ar] = a.y;
            As[(ak + 2) * 128 + ar] = a.z;
            As[(ak + 3) * 128 + ar] = a.w;
        }
        {
            float4 w = *(const float4*)&W[(size_t)(n0 + war) * K + k0 + wak];
            Ws[(wak + 0) * 64 + war] = w.x;
            Ws[(wak + 1) * 64 + war] = w.y;
            Ws[(wak + 2) * 64 + war] = w.z;
            Ws[(wak + 3) * 64 + war] = w.w;
        }
        __syncthreads();
#pragma unroll
        for (int k = 0; k < 16; k++) {
            float4 av0 = *(const float4*)&As[k * 128 + ty * 8];
            float4 av1 = *(const float4*)&As[k * 128 + ty * 8 + 4];
            ulonglong2 wv = *(const ulonglong2*)&Ws[k * 64 + tx * 4];
            float am[8] = {av0.x, av0.y, av0.z, av0.w, av1.x, av1.y, av1.z, av1.w};
#pragma unroll
            for (int i = 0; i < 8; i++) {
                unsigned long long ai = dup2(am[i]);
                acc[i][0] = fma2(ai, wv.x, acc[i][0]);
                acc[i][1] = fma2(ai, wv.y, acc[i][1]);
            }
        }
        __syncthreads();
    }

    float4 bv = *(const float4*)&bias[n0 + tx * 4];
#pragma unroll
    for (int i = 0; i < 8; i++) {
        int m = m0 + ty * 8 + i;
        float c0, c1, c2, c3;
        unpack2(acc[i][0], c0, c1);
        unpack2(acc[i][1], c2, c3);
        float4 o;
        o.x = c0 + bv.x; o.y = c1 + bv.y; o.z = c2 + bv.z; o.w = c3 + bv.w;
        *(float4*)&out[(size_t)m * N + n0 + tx * 4] = o;
    }
}

// -------- 8-CTA row-group sense barrier --------
__device__ __forceinline__ void group_barrier(int g, unsigned target)
{
    __syncthreads();
    if (threadIdx.x == 0) {
        __threadfence();
        unsigned prev = atomicAdd(&g_bar_count[g], 1u);
        if (prev == STRIPS - 1) {
            atomicExch(&g_bar_count[g], 0u);
            __threadfence();
            atomicAdd(&g_bar_gen[g], 1u);
        } else {
            while (*((volatile unsigned*)&g_bar_gen[g]) < target) { }
            __threadfence();
        }
    }
    __syncthreads();
}

// -------- persistent GRU layer --------
// 128 CTAs = 16 rowtiles x 8 strips. CTA tile: 16 rows x (32 cols x 3 gates).
// Warp w: cols w*8..w*8+7. Lane: c=l&7 (col), q=l>>3 (K-quarter of 64).
// Each warp covers all 16 rows -> W smem read ONCE per CTA per step.
__global__ __launch_bounds__(128, 1) void gru_layer(
    const float* __restrict__ xp,
    const float* __restrict__ Whh,
    const float* __restrict__ bhh,
    float* __restrict__ h_seq,
    float* __restrict__ h_final)
{
    extern __shared__ float sm[];
    float* sW = sm;                  // [4 quarters][96 rows][68]
    float* sH = sm + 4 * QSTRIDE;    // [16][256]
    float* sRed = sm + RED_OFF;      // [2 halves][4 warps][24][33]

    const int cta = blockIdx.x;
    const int rowtile = cta >> 3;
    const int strip = cta & 7;
    const int j0 = strip * 32;
    const int r0 = rowtile * 16;
    const int tid = threadIdx.x;
    const int w = tid >> 5;
    const int l = tid & 31;
    const int c = l & 7;
    const int q = l >> 3;
    const int wcol = (w << 3) + c;
    const int jj = j0 + wcol;

    // Preload W_hh into [quarter][row][68] layout.
    for (int i = tid; i < 96 * 64; i += 128) {
        int wr = i >> 6;              // 0..95 = g*32 + jc
        int m = i & 63;               // float4 index within row (k = m*4)
        int qq = m >> 4;
        int kk = (m & 15) << 2;
        int g = wr >> 5, jc = wr & 31;
        float4 v = *(const float4*)&Whh[(size_t)(g * H + j0 + jc) * H + (m << 2)];
        *(float4*)&sW[qq * QSTRIDE + wr * WROW + kk] = v;
    }
    const float bhr = bhh[jj];
    const float bhz = bhh[H + jj];
    const float bhn = bhh[2 * H + jj];

    const float* wrp = sW + q * QSTRIDE + wcol * WROW;
    const float* wzp = wrp + 32 * WROW;
    const float* wnp = wrp + 64 * WROW;

    // zero h0 slice (16 rows x 32 cols)
    for (int i = tid; i < 16 * 32; i += 128) {
        int rr = i >> 5, cc = i & 31;
        g_hbuf[(size_t)(r0 + rr) * H + j0 + cc] = 0.f;
    }

    unsigned target = *((volatile unsigned*)&g_bar_gen[rowtile]);
    target++;
    group_barrier(rowtile, target);

    for (int t = 0; t < S; t++) {
        const float* hcur = g_hbuf + (size_t)(t & 1) * (B * H);
        float* hnext = g_hbuf + (size_t)((t + 1) & 1) * (B * H);

        // prefetch xp for this lane's 4 rows (2 per half)
        float px[4][3];
#pragma unroll
        for (int hf = 0; hf < 2; hf++)
#pragma unroll
            for (int u = 0; u < 2; u++) {
                int idx = hf * 2 + u;
                int row = hf * 8 + q * 2 + u;
                size_t xb = ((size_t)(r0 + row) * S + t) * G3 + jj;
                px[idx][0] = __ldg(&xp[xb]);
                px[idx][1] = __ldg(&xp[xb + H]);
                px[idx][2] = __ldg(&xp[xb + 2 * H]);
            }

        // stage h tile (16 x 256), L2-coherent
        for (int i = tid; i < 16 * 64; i += 128) {
            int rr = i >> 6, k4 = (i & 63) << 2;
            float4 v = __ldcg((const float4*)&hcur[(size_t)(r0 + rr) * H + k4]);
            *(float4*)&sH[rr * SH_STRIDE + k4] = v;
        }
        __syncthreads();

#pragma unroll
        for (int hf = 0; hf < 2; hf++) {
            unsigned long long acc[8][3];
#pragma unroll
            for (int r = 0; r < 8; r++) {
                acc[r][0] = 0ull; acc[r][1] = 0ull; acc[r][2] = 0ull;
            }
            const float* hbase = sH + hf * 8 * SH_STRIDE + (q << 6);
#pragma unroll 4
            for (int k = 0; k < 64; k += 4) {
                ulonglong2 wrv = *(const ulonglong2*)(wrp + k);
                ulonglong2 wzv = *(const ulonglong2*)(wzp + k);
                ulonglong2 wnv = *(const ulonglong2*)(wnp + k);
#pragma unroll
                for (int r = 0; r < 8; r++) {
                    ulonglong2 hv = *(const ulonglong2*)(hbase + r * SH_STRIDE + k);
                    acc[r][0] = fma2(hv.x, wrv.x, acc[r][0]);
                    acc[r][0] = fma2(hv.y, wrv.y, acc[r][0]);
                    acc[r][1] = fma2(hv.x, wzv.x, acc[r][1]);
                    acc[r][1] = fma2(hv.y, wzv.y, acc[r][1]);
                    acc[r][2] = fma2(hv.x, wnv.x, acc[r][2]);
                    acc[r][2] = fma2(hv.y, wnv.y, acc[r][2]);
                }
            }

            // per-warp smem transpose reduction over K-quarters
            float* red = sRed + (hf * 4 + w) * (24 * RED_STRIDE);
#pragma unroll
            for (int r = 0; r < 8; r++)
#pragma unroll
                for (int g = 0; g < 3; g++)
                    red[(r * 3 + g) * RED_STRIDE + l] = hsum2(acc[r][g]);
            __syncwarp();

#pragma unroll
            for (int u = 0; u < 2; u++) {
                int rl = q * 2 + u;            // row within half
                int idx = hf * 2 + u;
                float sr = 0.f, sz = 0.f, sn = 0.f;
#pragma unroll
                for (int qq = 0; qq < 4; qq++) {
                    int o = qq * 8 + c;
                    sr += red[(rl * 3 + 0) * RED_STRIDE + o];
                    sz += red[(rl * 3 + 1) * RED_STRIDE + o];
                    sn += red[(rl * 3 + 2) * RED_STRIDE + o];
                }
                float rg = sigmoid_ap(px[idx][0] + sr + bhr);
                float zg = sigmoid_ap(px[idx][1] + sz + bhz);
                float ng = tanh_ap(px[idx][2] + rg * (sn + bhn));
                int rloc = hf * 8 + rl;
                float hold = sH[rloc * SH_STRIDE + jj];
                float hnew = (1.f - zg) * ng + zg * hold;
                size_t grow = r0 + rloc;
                hnext[grow * H + jj] = hnew;
                if (h_seq) h_seq[(grow * S + t) * H + jj] = hnew;
                if (h_final && t == S - 1) h_final[grow * H + jj] = hnew;
            }
        }

        target++;
        group_barrier(rowtile, target);
    }
}

// -------- projection + forecast --------
__global__ void forecast_kernel(
    const float* __restrict__ h2, const float* __restrict__ Wp,
    const float* __restrict__ bp, const float* __restrict__ C,
    const float* __restrict__ rld, const float* __restrict__ rtd,
    const float* __restrict__ rg_, const float* __restrict__ om,
    float* __restrict__ out)
{
    const int b = blockIdx.x;
    const int d = threadIdx.x;
    __shared__ float sh[H];
    for (int i = d; i < H; i += 32) sh[i] = h2[(size_t)b * H + i];
    __syncthreads();

    float s[NSTATE];
#pragma unroll
    for (int st = 0; st < NSTATE; st++) {
        const float* w = Wp + (size_t)(d * NSTATE + st) * H;
        float acc = bp[d * NSTATE + st];
        for (int k = 0; k < H; k += 4) {
            float4 wv = *(const float4*)(w + k);
            acc += sh[k] * wv.x + sh[k + 1] * wv.y + sh[k + 2] * wv.z + sh[k + 3] * wv.w;
        }
        s[st] = acc;
    }

    float al = 1.f / (1.f + expf(-rld[d])) * 0.15f + 0.85f;
    float at = 1.f / (1.f + expf(-rtd[d])) * 0.25f + 0.70f;
    float gg = 1.f / (1.f + expf(-rg_[d])) * 0.20f + 0.80f;
    float cc = cosf(om[d]), sn = sinf(om[d]);
    float r00 = gg * cc, r01 = -gg * sn, r10 = gg * sn, r11 = gg * cc;
    float C0 = C[d * 4 + 0], C1 = C[d * 4 + 1], C2 = C[d * 4 + 2], C3 = C[d * 4 + 3];

    for (int p = 0; p < PRED; p++) {
        float n0 = s[0] * al;
        float n1 = s[1] * at;
        float n2 = s[2] * r00 + s[3] * r10;
        float n3 = s[2] * r01 + s[3] * r11;
        s[0] = n0; s[1] = n1; s[2] = n2; s[3] = n3;
        out[((size_t)b * PRED + p) * D_OUT + d] = C0 * n0 + C1 * n1 + C2 * n2 + C3 * n3;
    }
}

extern "C" void kernel_launch(void* const* d_in, const int* in_sizes, int n_in,
                              void* d_out, int out_size)
{
    const float* x    = (const float*)d_in[0];
    const float* Wih0 = (const float*)d_in[1];
    const float* Whh0 = (const float*)d_in[2];
    const float* bih0 = (const float*)d_in[3];
    const float* bhh0 = (const float*)d_in[4];
    const float* Wih1 = (const float*)d_in[5];
    const float* Whh1 = (const float*)d_in[6];
    const float* bih1 = (const float*)d_in[7];
    const float* bhh1 = (const float*)d_in[8];
    const float* Wp   = (const float*)d_in[9];
    const float* bp   = (const float*)d_in[10];
    const float* C    = (const float*)d_in[11];
    const float* rld  = (const float*)d_in[12];
    const float* rtd  = (const float*)d_in[13];
    const float* rg   = (const float*)d_in[14];
    const float* om   = (const float*)d_in[15];
    float* out = (float*)d_out;

    float *xp, *h1s, *h2;
    cudaGetSymbolAddress((void**)&xp, g_xp);
    cudaGetSymbolAddress((void**)&h1s, g_h1s);
    cudaGetSymbolAddress((void**)&h2, g_h2);

    cudaFuncSetAttribute(gru_layer, cudaFuncAttributeMaxDynamicSharedMemorySize, SMEM_BYTES);

    dim3 gg(G3 / 64, (B * S) / 128);

    gemm_nt_bias<<<gg, 256>>>(x, Wih0, bih0, xp, B * S, G3, IN_F);
    gru_layer<<<GRU_CTAS, 128, SMEM_BYTES>>>(xp, Whh0, bhh0, h1s, nullptr);
    gemm_nt_bias<<<gg, 256>>>(h1s, Wih1, bih1, xp, B * S, G3, H);
    gru_layer<<<GRU_CTAS, 128, SMEM_BYTES>>>(xp, Whh1, bhh1, nullptr, h2);
    forecast_kernel<<<B, 32>>>(h2, Wp, bp, C, rld, rtd, rg, om, out);
}